// round 1
// baseline (speedup 1.0000x reference)
#include <cuda_runtime.h>
#include <math.h>

#define N_NODES 20000
#define F_IN    512
#define HDIM    64
#define L_LAYERS 8
#define E_EDGES 640000
#define C_OUT   40

// ---------------- device scratch (no runtime allocation allowed) ----------------
__device__ float g_h0[N_NODES * HDIM];
__device__ float g_hA[N_NODES * HDIM];
__device__ float g_hB[N_NODES * HDIM];
__device__ int   g_cnt[N_NODES];
__device__ int   g_ptr[N_NODES + 1];
__device__ int   g_cursor[N_NODES];
__device__ int2  g_edges[E_EDGES];          // x = col index, y = float bits of weight
__device__ float g_Wt[C_OUT * HDIM * HDIM]; // transposed lin1_w: [k][i*64+j]

// ---------------- CSR build ----------------
__global__ void zero_cnt_kernel() {
    int i = blockIdx.x * blockDim.x + threadIdx.x;
    if (i < N_NODES) g_cnt[i] = 0;
}

__global__ void hist_kernel(const int* __restrict__ row) {
    int e = blockIdx.x * blockDim.x + threadIdx.x;
    if (e < E_EDGES) atomicAdd(&g_cnt[row[e]], 1);
}

// single-block exclusive scan over 20000 counters -> g_ptr, g_cursor
__global__ void scan_kernel() {
    const int T = 512;
    const int PER = (N_NODES + T - 1) / T;  // 40
    __shared__ int sums[T];
    int t = threadIdx.x;
    int base = t * PER;
    int local[PER];
    int s = 0;
#pragma unroll
    for (int i = 0; i < PER; i++) {
        int idx = base + i;
        int v = (idx < N_NODES) ? g_cnt[idx] : 0;
        local[i] = s;
        s += v;
    }
    sums[t] = s;
    __syncthreads();
    // Hillis-Steele inclusive scan
    for (int off = 1; off < T; off <<= 1) {
        int v = (t >= off) ? sums[t - off] : 0;
        __syncthreads();
        sums[t] += v;
        __syncthreads();
    }
    int offset = (t == 0) ? 0 : sums[t - 1];
#pragma unroll
    for (int i = 0; i < PER; i++) {
        int idx = base + i;
        if (idx < N_NODES) {
            int p = offset + local[i];
            g_ptr[idx] = p;
            g_cursor[idx] = p;
        }
    }
    if (t == T - 1) g_ptr[N_NODES] = sums[T - 1];
}

__global__ void scatter_kernel(const int* __restrict__ row, const int* __restrict__ col,
                               const float* __restrict__ ew) {
    int e = blockIdx.x * blockDim.x + threadIdx.x;
    if (e < E_EDGES) {
        int r = row[e];
        int pos = atomicAdd(&g_cursor[r], 1);
        g_edges[pos] = make_int2(col[e], __float_as_int(ew[e]));
    }
}

// ---------------- transpose lin1_w [4096,40] -> g_Wt [40][4096] ----------------
__global__ void transpose_kernel(const float* __restrict__ w) {
    int idx = blockIdx.x * blockDim.x + threadIdx.x;  // 0 .. 163839
    if (idx < C_OUT * HDIM * HDIM) {
        int p = idx / C_OUT;
        int k = idx % C_OUT;
        g_Wt[k * (HDIM * HDIM) + p] = w[idx];  // read coalesced, write strided (cheap, one-time)
    }
}

// ---------------- lin0 GEMM: h0 = relu(x @ W + b) ; also seed h ----------------
// block 256 threads computes 128 rows x 64 cols, BK = 32
__global__ void lin0_kernel(const float* __restrict__ x, const float* __restrict__ w,
                            const float* __restrict__ b) {
    __shared__ float Xs[32][137];   // transposed x tile (pad 137 -> conflict-free)
    __shared__ float Ws[32][64];
    int tid = threadIdx.x;
    int tx = tid & 15;         // 16 col-groups of 4
    int ty = tid >> 4;         // 16 row-groups of 8
    int row0 = blockIdx.x * 128;
    float acc[8][4];
#pragma unroll
    for (int m = 0; m < 8; m++)
#pragma unroll
        for (int n = 0; n < 4; n++) acc[m][n] = 0.f;

    for (int k0 = 0; k0 < F_IN; k0 += 32) {
        // load X tile (128 rows x 32 k), store transposed
#pragma unroll
        for (int q = 0; q < 4; q++) {
            int idx = tid + 256 * q;       // 0..1023 float4 slots
            int r = idx >> 3;
            int k4 = idx & 7;
            int gr = row0 + r;
            float4 v = make_float4(0.f, 0.f, 0.f, 0.f);
            if (gr < N_NODES) v = *(const float4*)&x[gr * F_IN + k0 + k4 * 4];
            Xs[k4 * 4 + 0][r] = v.x;
            Xs[k4 * 4 + 1][r] = v.y;
            Xs[k4 * 4 + 2][r] = v.z;
            Xs[k4 * 4 + 3][r] = v.w;
        }
        // load W tile (32 x 64)
#pragma unroll
        for (int q = 0; q < 2; q++) {
            int idx = tid + 256 * q;       // 0..511 float4 slots
            int kk = idx >> 4;
            int c4 = idx & 15;
            *(float4*)&Ws[kk][c4 * 4] = *(const float4*)&w[(k0 + kk) * HDIM + c4 * 4];
        }
        __syncthreads();
#pragma unroll
        for (int kk = 0; kk < 32; kk++) {
            float a[8];
#pragma unroll
            for (int m = 0; m < 8; m++) a[m] = Xs[kk][ty * 8 + m];
            float4 b4 = *(float4*)&Ws[kk][tx * 4];
            float bb[4] = {b4.x, b4.y, b4.z, b4.w};
#pragma unroll
            for (int m = 0; m < 8; m++)
#pragma unroll
                for (int n = 0; n < 4; n++) acc[m][n] = fmaf(a[m], bb[n], acc[m][n]);
        }
        __syncthreads();
    }
#pragma unroll
    for (int m = 0; m < 8; m++) {
        int gr = row0 + ty * 8 + m;
        if (gr < N_NODES) {
#pragma unroll
            for (int n = 0; n < 4; n++) {
                int c = tx * 4 + n;
                float v = fmaxf(acc[m][n] + b[c], 0.f);
                g_h0[gr * HDIM + c] = v;
                g_hA[gr * HDIM + c] = v;
            }
        }
    }
}

// ---------------- fused GCN2 layer: spmm(CSR) + initial residual + conv + relu ----------------
// one warp per node; lane owns columns lane and lane+32
__global__ void layer_kernel(const float* __restrict__ hin, float* __restrict__ hout,
                             const float* __restrict__ convw, float one_minus_beta, float beta) {
    __shared__ float Wc[64][64];
    int tid = threadIdx.x;
#pragma unroll
    for (int q = 0; q < 4; q++) {
        int idx = tid + 256 * q;           // 1024 float4 slots
        *(float4*)&Wc[0][idx * 4] = *(const float4*)&convw[idx * 4];
    }
    __syncthreads();

    int warp = tid >> 5, lane = tid & 31;
    int node = blockIdx.x * 8 + warp;
    if (node >= N_NODES) return;

    int s = g_ptr[node];
    int e = g_ptr[node + 1];
    float acc0 = 0.f, acc1 = 0.f;
    int i = s;
    for (; i + 4 <= e; i += 4) {
        int2 a0 = g_edges[i];
        int2 a1 = g_edges[i + 1];
        int2 a2 = g_edges[i + 2];
        int2 a3 = g_edges[i + 3];
        float v00 = __ldg(&hin[a0.x * HDIM + lane]);
        float v01 = __ldg(&hin[a0.x * HDIM + 32 + lane]);
        float v10 = __ldg(&hin[a1.x * HDIM + lane]);
        float v11 = __ldg(&hin[a1.x * HDIM + 32 + lane]);
        float v20 = __ldg(&hin[a2.x * HDIM + lane]);
        float v21 = __ldg(&hin[a2.x * HDIM + 32 + lane]);
        float v30 = __ldg(&hin[a3.x * HDIM + lane]);
        float v31 = __ldg(&hin[a3.x * HDIM + 32 + lane]);
        acc0 = fmaf(__int_as_float(a0.y), v00, acc0);
        acc1 = fmaf(__int_as_float(a0.y), v01, acc1);
        acc0 = fmaf(__int_as_float(a1.y), v10, acc0);
        acc1 = fmaf(__int_as_float(a1.y), v11, acc1);
        acc0 = fmaf(__int_as_float(a2.y), v20, acc0);
        acc1 = fmaf(__int_as_float(a2.y), v21, acc1);
        acc0 = fmaf(__int_as_float(a3.y), v30, acc0);
        acc1 = fmaf(__int_as_float(a3.y), v31, acc1);
    }
    for (; i < e; i++) {
        int2 a0 = g_edges[i];
        float wv = __int_as_float(a0.y);
        acc0 = fmaf(wv, __ldg(&hin[a0.x * HDIM + lane]), acc0);
        acc1 = fmaf(wv, __ldg(&hin[a0.x * HDIM + 32 + lane]), acc1);
    }

    float o0 = 0.9f * acc0 + 0.1f * g_h0[node * HDIM + lane];
    float o1 = 0.9f * acc1 + 0.1f * g_h0[node * HDIM + 32 + lane];

    // conv: hn[c] = sum_k out[k] * Wc[k][c], out[k] distributed across lanes
    float gg0 = 0.f, gg1 = 0.f;
#pragma unroll
    for (int k = 0; k < 32; k++) {
        float ok = __shfl_sync(0xffffffffu, o0, k);
        gg0 = fmaf(ok, Wc[k][lane], gg0);
        gg1 = fmaf(ok, Wc[k][lane + 32], gg1);
    }
#pragma unroll
    for (int k = 0; k < 32; k++) {
        float ok = __shfl_sync(0xffffffffu, o1, k);
        gg0 = fmaf(ok, Wc[32 + k][lane], gg0);
        gg1 = fmaf(ok, Wc[32 + k][lane + 32], gg1);
    }
    float r0 = fmaxf(one_minus_beta * o0 + beta * gg0, 0.f);
    float r1 = fmaxf(one_minus_beta * o1 + beta * gg1, 0.f);
    hout[node * HDIM + lane] = r0;
    hout[node * HDIM + 32 + lane] = r1;
}

// ---------------- final: bilinear z = h^T W_k h, hyperbolic maps, log_softmax ----------------
// block: 256 threads, 64 nodes; W staged in smem, 4 k's at a time
#define FK_HS_STRIDE 68
#define FK_W_STRIDE  4104
#define FK_SMEM_FLOATS (64 * FK_HS_STRIDE + 64 * C_OUT + 64 + 4 * FK_W_STRIDE)
#define FK_SMEM_BYTES  (FK_SMEM_FLOATS * 4)

__global__ void final_kernel(const float* __restrict__ hin, const float* __restrict__ b1,
                             float* __restrict__ out) {
    extern __shared__ float smem[];
    float* hs  = smem;                          // [64][68]
    float* zs  = hs + 64 * FK_HS_STRIDE;        // [64][40]
    float* n2s = zs + 64 * C_OUT;               // [64]
    float* ws  = n2s + 64;                      // [4][4104]

    int tid = threadIdx.x;
    int n0 = blockIdx.x * 64;

    // load h tile
#pragma unroll
    for (int q = 0; q < 16; q++) {
        int idx = tid + 256 * q;        // 0..4095
        int nd = idx >> 6;
        int j = idx & 63;
        int gn = n0 + nd;
        float v = (gn < N_NODES) ? hin[gn * HDIM + j] : 0.f;
        hs[nd * FK_HS_STRIDE + j] = v;
    }
    __syncthreads();

    if (tid < 64) {
        float s = 0.f;
        const float* hr = hs + tid * FK_HS_STRIDE;
#pragma unroll
        for (int j = 0; j < 64; j++) s = fmaf(hr[j], hr[j], s);
        n2s[tid] = s;
    }

    int node = tid >> 2;
    int kk = tid & 3;
    bool valid = (n0 + node) < N_NODES;
    const float* hrow = hs + node * FK_HS_STRIDE;

    for (int kc = 0; kc < C_OUT; kc += 4) {
        __syncthreads();  // protect ws from readers of previous chunk
        // load 4 x 4096 W chunk
#pragma unroll
        for (int q = 0; q < 16; q++) {
            int v = tid + 256 * q;      // float4 slot 0..4095
            int c = v >> 10;
            int p4 = v & 1023;
            float4 wv = *(const float4*)&g_Wt[(kc + c) * (HDIM * HDIM) + p4 * 4];
            *(float4*)&ws[c * FK_W_STRIDE + p4 * 4] = wv;
        }
        __syncthreads();

        float z = 0.f;
        if (valid) {
            const float* wrow = ws + kk * FK_W_STRIDE;
#pragma unroll 2
            for (int ii = 0; ii < 64; ii++) {
                float hi = hrow[ii];
                const float* wr = wrow + ii * 64;
                float zi = 0.f;
#pragma unroll
                for (int j4 = 0; j4 < 16; j4++) {
                    float4 w4 = *(const float4*)(wr + j4 * 4);
                    float4 h4 = *(const float4*)(hrow + j4 * 4);
                    zi = fmaf(w4.x, h4.x, zi);
                    zi = fmaf(w4.y, h4.y, zi);
                    zi = fmaf(w4.z, h4.z, zi);
                    zi = fmaf(w4.w, h4.w, zi);
                }
                z = fmaf(hi, zi, z);
            }
        }
        zs[node * C_OUT + kc + kk] = z;
    }
    __syncthreads();

    // per-node hyperbolic epilogue + log_softmax
    if (tid < 64) {
        int gn = n0 + tid;
        if (gn < N_NODES) {
            const float MAXN = 1.0f - 4e-3f;   // (1-PROJ_EPS)/sqrt(c), c=1
            float n2 = fmaxf(n2s[tid], 1e-15f);
            float pn = fminf(n2, MAXN);
            float t = atanhf(pn);
            float scale = t / n2;

            float u[C_OUT];
            float un2 = 0.f;
#pragma unroll
            for (int k = 0; k < C_OUT; k++) {
                float v = scale * zs[tid * C_OUT + k] + b1[k];
                u[k] = v;
                un2 = fmaf(v, v, un2);
            }
            float un = fmaxf(sqrtf(un2), 1e-15f);
            float th = tanhf(un);
            float g = fminf(th, MAXN) / un;    // expmap0 followed by proj

            float m = -INFINITY;
#pragma unroll
            for (int k = 0; k < C_OUT; k++) {
                u[k] *= g;
                m = fmaxf(m, u[k]);
            }
            float se = 0.f;
#pragma unroll
            for (int k = 0; k < C_OUT; k++) se += expf(u[k] - m);
            float lse = m + logf(se);
#pragma unroll
            for (int k = 0; k < C_OUT; k++) out[gn * C_OUT + k] = u[k] - lse;
        }
    }
}

// ---------------- launch ----------------
extern "C" void kernel_launch(void* const* d_in, const int* in_sizes, int n_in,
                              void* d_out, int out_size) {
    const float* x      = (const float*)d_in[0];
    const int*   row    = (const int*)d_in[1];
    const int*   col    = (const int*)d_in[2];
    const float* ew     = (const float*)d_in[3];
    const float* lin0_w = (const float*)d_in[4];
    const float* lin0_b = (const float*)d_in[5];
    const float* conv_w = (const float*)d_in[6];
    const float* lin1_w = (const float*)d_in[7];
    const float* lin1_b = (const float*)d_in[8];
    float* out = (float*)d_out;

    float* hA = nullptr;
    float* hB = nullptr;
    cudaGetSymbolAddress((void**)&hA, g_hA);
    cudaGetSymbolAddress((void**)&hB, g_hB);

    // CSR build
    zero_cnt_kernel<<<(N_NODES + 255) / 256, 256>>>();
    hist_kernel<<<(E_EDGES + 255) / 256, 256>>>(row);
    scan_kernel<<<1, 512>>>();
    scatter_kernel<<<(E_EDGES + 255) / 256, 256>>>(row, col, ew);

    // weight transpose for the final bilinear
    transpose_kernel<<<(C_OUT * HDIM * HDIM + 255) / 256, 256>>>(lin1_w);

    // lin0 (writes g_h0 and g_hA)
    lin0_kernel<<<(N_NODES + 127) / 128, 256>>>(x, lin0_w, lin0_b);

    // 8 fused GCN2 layers, ping-pong hA/hB
    const float* hin = hA;
    float* hout = hB;
    for (int l = 0; l < L_LAYERS; l++) {
        float beta = logf(0.5f / (float)(l + 1) + 1.0f);
        layer_kernel<<<(N_NODES + 7) / 8, 256>>>(hin, hout, conv_w + l * HDIM * HDIM,
                                                 1.0f - beta, beta);
        const float* tmp = hin;
        hin = hout;
        hout = (float*)tmp;
    }

    // final fused bilinear + hyperbolic + log_softmax
    cudaFuncSetAttribute(final_kernel, cudaFuncAttributeMaxDynamicSharedMemorySize,
                         FK_SMEM_BYTES);
    final_kernel<<<(N_NODES + 63) / 64, 256, FK_SMEM_BYTES>>>(hin, lin1_b, out);
}

// round 2
// speedup vs baseline: 1.4634x; 1.4634x over previous
#include <cuda_runtime.h>
#include <math.h>

#define N_NODES 20000
#define F_IN    512
#define HDIM    64
#define L_LAYERS 8
#define E_EDGES 640000
#define C_OUT   40
#define NPAIR   2080          // 64*65/2 pairs (i<=j)

// ---------------- device scratch (no runtime allocation allowed) ----------------
__device__ float g_h0[N_NODES * HDIM];
__device__ float g_hA[N_NODES * HDIM];
__device__ float g_hB[N_NODES * HDIM];
__device__ int   g_cnt[N_NODES];
__device__ int   g_ptr[N_NODES + 1];
__device__ int   g_cursor[N_NODES];
__device__ int2  g_edges[E_EDGES];            // x = col index, y = float bits of weight
__device__ int   g_pi[NPAIR];
__device__ int   g_pj[NPAIR];
__device__ float g_Apack[NPAIR * 80];         // [p][k][2] duplicated symmetric weights

#define FMA_F32X2(d, a, b, c) \
    asm("fma.rn.f32x2 %0, %1, %2, %3;" : "=l"(d) : "l"(a), "l"(b), "l"(c))

// ---------------- CSR build ----------------
__global__ void zero_cnt_kernel() {
    int i = blockIdx.x * blockDim.x + threadIdx.x;
    if (i < N_NODES) g_cnt[i] = 0;
}

__global__ void hist_kernel(const int* __restrict__ row) {
    int e = blockIdx.x * blockDim.x + threadIdx.x;
    if (e < E_EDGES) atomicAdd(&g_cnt[row[e]], 1);
}

__global__ void scan_kernel() {
    const int T = 512;
    const int PER = (N_NODES + T - 1) / T;  // 40
    __shared__ int sums[T];
    int t = threadIdx.x;
    int base = t * PER;
    int local[PER];
    int s = 0;
#pragma unroll
    for (int i = 0; i < PER; i++) {
        int idx = base + i;
        int v = (idx < N_NODES) ? g_cnt[idx] : 0;
        local[i] = s;
        s += v;
    }
    sums[t] = s;
    __syncthreads();
    for (int off = 1; off < T; off <<= 1) {
        int v = (t >= off) ? sums[t - off] : 0;
        __syncthreads();
        sums[t] += v;
        __syncthreads();
    }
    int offset = (t == 0) ? 0 : sums[t - 1];
#pragma unroll
    for (int i = 0; i < PER; i++) {
        int idx = base + i;
        if (idx < N_NODES) {
            int p = offset + local[i];
            g_ptr[idx] = p;
            g_cursor[idx] = p;
        }
    }
    if (t == T - 1) g_ptr[N_NODES] = sums[T - 1];
}

__global__ void scatter_kernel(const int* __restrict__ row, const int* __restrict__ col,
                               const float* __restrict__ ew) {
    int e = blockIdx.x * blockDim.x + threadIdx.x;
    if (e < E_EDGES) {
        int r = row[e];
        int pos = atomicAdd(&g_cursor[r], 1);
        g_edges[pos] = make_int2(col[e], __float_as_int(ew[e]));
    }
}

// ---------------- pair tables + symmetric packed A ----------------
__global__ void pairs_kernel() {
    int p = blockIdx.x * blockDim.x + threadIdx.x;
    if (p < NPAIR) {
        int i = 0, off = 0;
        while (off + (HDIM - i) <= p) { off += HDIM - i; i++; }
        g_pi[p] = i;
        g_pj[p] = i + (p - off);
    }
}

// A[p][k] = W[(i,j),k] + (i!=j ? W[(j,i),k] : 0), duplicated into 2 adjacent floats
__global__ void apack_kernel(const float* __restrict__ lin1_w) {
    int idx = blockIdx.x * blockDim.x + threadIdx.x;   // 0 .. 83199
    if (idx < NPAIR * C_OUT) {
        int p = idx / C_OUT;
        int k = idx % C_OUT;
        int i = g_pi[p], j = g_pj[p];
        float v = lin1_w[(i * HDIM + j) * C_OUT + k];
        if (i != j) v += lin1_w[(j * HDIM + i) * C_OUT + k];
        g_Apack[p * 80 + 2 * k]     = v;
        g_Apack[p * 80 + 2 * k + 1] = v;
    }
}

// ---------------- lin0 GEMM: h0 = relu(x @ W + b) ; also seed h ----------------
__global__ void lin0_kernel(const float* __restrict__ x, const float* __restrict__ w,
                            const float* __restrict__ b) {
    __shared__ float Xs[32][137];
    __shared__ float Ws[32][64];
    int tid = threadIdx.x;
    int tx = tid & 15;
    int ty = tid >> 4;
    int row0 = blockIdx.x * 128;
    float acc[8][4];
#pragma unroll
    for (int m = 0; m < 8; m++)
#pragma unroll
        for (int n = 0; n < 4; n++) acc[m][n] = 0.f;

    for (int k0 = 0; k0 < F_IN; k0 += 32) {
#pragma unroll
        for (int q = 0; q < 4; q++) {
            int idx = tid + 256 * q;
            int r = idx >> 3;
            int k4 = idx & 7;
            int gr = row0 + r;
            float4 v = make_float4(0.f, 0.f, 0.f, 0.f);
            if (gr < N_NODES) v = *(const float4*)&x[gr * F_IN + k0 + k4 * 4];
            Xs[k4 * 4 + 0][r] = v.x;
            Xs[k4 * 4 + 1][r] = v.y;
            Xs[k4 * 4 + 2][r] = v.z;
            Xs[k4 * 4 + 3][r] = v.w;
        }
#pragma unroll
        for (int q = 0; q < 2; q++) {
            int idx = tid + 256 * q;
            int kk = idx >> 4;
            int c4 = idx & 15;
            *(float4*)&Ws[kk][c4 * 4] = *(const float4*)&w[(k0 + kk) * HDIM + c4 * 4];
        }
        __syncthreads();
#pragma unroll
        for (int kk = 0; kk < 32; kk++) {
            float a[8];
#pragma unroll
            for (int m = 0; m < 8; m++) a[m] = Xs[kk][ty * 8 + m];
            float4 b4 = *(float4*)&Ws[kk][tx * 4];
            float bb[4] = {b4.x, b4.y, b4.z, b4.w};
#pragma unroll
            for (int m = 0; m < 8; m++)
#pragma unroll
                for (int n = 0; n < 4; n++) acc[m][n] = fmaf(a[m], bb[n], acc[m][n]);
        }
        __syncthreads();
    }
#pragma unroll
    for (int m = 0; m < 8; m++) {
        int gr = row0 + ty * 8 + m;
        if (gr < N_NODES) {
#pragma unroll
            for (int n = 0; n < 4; n++) {
                int c = tx * 4 + n;
                float v = fmaxf(acc[m][n] + b[c], 0.f);
                g_h0[gr * HDIM + c] = v;
                g_hA[gr * HDIM + c] = v;
            }
        }
    }
}

// ---------------- fused GCN2 layer: spmm(CSR) + initial residual + conv + relu ----------------
__global__ void layer_kernel(const float* __restrict__ hin, float* __restrict__ hout,
                             const float* __restrict__ convw, float one_minus_beta, float beta) {
    __shared__ float Wc[64][64];
    int tid = threadIdx.x;
#pragma unroll
    for (int q = 0; q < 4; q++) {
        int idx = tid + 256 * q;
        *(float4*)&Wc[0][idx * 4] = *(const float4*)&convw[idx * 4];
    }
    __syncthreads();

    int warp = tid >> 5, lane = tid & 31;
    int node = blockIdx.x * 8 + warp;
    if (node >= N_NODES) return;

    int s = g_ptr[node];
    int e = g_ptr[node + 1];
    float acc0 = 0.f, acc1 = 0.f;
    int i = s;
    // peel to even index for int4 (2-edge) loads
    if ((i & 1) && i < e) {
        int2 a0 = g_edges[i];
        float wv = __int_as_float(a0.y);
        acc0 = fmaf(wv, __ldg(&hin[a0.x * HDIM + lane]), acc0);
        acc1 = fmaf(wv, __ldg(&hin[a0.x * HDIM + 32 + lane]), acc1);
        i++;
    }
    for (; i + 4 <= e; i += 4) {
        int4 e01 = *(const int4*)&g_edges[i];
        int4 e23 = *(const int4*)&g_edges[i + 2];
        float v00 = __ldg(&hin[e01.x * HDIM + lane]);
        float v01 = __ldg(&hin[e01.x * HDIM + 32 + lane]);
        float v10 = __ldg(&hin[e01.z * HDIM + lane]);
        float v11 = __ldg(&hin[e01.z * HDIM + 32 + lane]);
        float v20 = __ldg(&hin[e23.x * HDIM + lane]);
        float v21 = __ldg(&hin[e23.x * HDIM + 32 + lane]);
        float v30 = __ldg(&hin[e23.z * HDIM + lane]);
        float v31 = __ldg(&hin[e23.z * HDIM + 32 + lane]);
        acc0 = fmaf(__int_as_float(e01.y), v00, acc0);
        acc1 = fmaf(__int_as_float(e01.y), v01, acc1);
        acc0 = fmaf(__int_as_float(e01.w), v10, acc0);
        acc1 = fmaf(__int_as_float(e01.w), v11, acc1);
        acc0 = fmaf(__int_as_float(e23.y), v20, acc0);
        acc1 = fmaf(__int_as_float(e23.y), v21, acc1);
        acc0 = fmaf(__int_as_float(e23.w), v30, acc0);
        acc1 = fmaf(__int_as_float(e23.w), v31, acc1);
    }
    for (; i < e; i++) {
        int2 a0 = g_edges[i];
        float wv = __int_as_float(a0.y);
        acc0 = fmaf(wv, __ldg(&hin[a0.x * HDIM + lane]), acc0);
        acc1 = fmaf(wv, __ldg(&hin[a0.x * HDIM + 32 + lane]), acc1);
    }

    float o0 = 0.9f * acc0 + 0.1f * g_h0[node * HDIM + lane];
    float o1 = 0.9f * acc1 + 0.1f * g_h0[node * HDIM + 32 + lane];

    float gg0 = 0.f, gg1 = 0.f;
#pragma unroll
    for (int k = 0; k < 32; k++) {
        float ok = __shfl_sync(0xffffffffu, o0, k);
        gg0 = fmaf(ok, Wc[k][lane], gg0);
        gg1 = fmaf(ok, Wc[k][lane + 32], gg1);
    }
#pragma unroll
    for (int k = 0; k < 32; k++) {
        float ok = __shfl_sync(0xffffffffu, o1, k);
        gg0 = fmaf(ok, Wc[32 + k][lane], gg0);
        gg1 = fmaf(ok, Wc[32 + k][lane + 32], gg1);
    }
    float r0 = fmaxf(one_minus_beta * o0 + beta * gg0, 0.f);
    float r1 = fmaxf(one_minus_beta * o1 + beta * gg1, 0.f);
    hout[node * HDIM + lane] = r0;
    hout[node * HDIM + 32 + lane] = r1;
}

// ---------------- final: z[n,k] = sum_p P[p,n]*A[p,k] (symmetric-pair GEMM) ----------------
// block: 256 threads, 128 nodes. Register tile per thread: 4 nodes (2 f32x2) x 5 k.
// KC = 32 pairs per chunk, 65 chunks exactly.
#define FM 128
#define KC 32
// smem float offsets
#define OFF_P   0                          // [KC][128]
#define OFF_A   (OFF_P + KC * FM)          // [KC][80]
#define OFF_H   (OFF_A + KC * 80)          // [128][65]
#define OFF_Z   (OFF_H + FM * 65)          // [128][40]
#define OFF_N2  (OFF_Z + FM * C_OUT)       // [128]
#define FK_SMEM_FLOATS (OFF_N2 + FM)
#define FK_SMEM_BYTES  (FK_SMEM_FLOATS * 4)

__global__ void final_kernel(const float* __restrict__ hin, const float* __restrict__ b1,
                             float* __restrict__ out) {
    extern __shared__ float smem[];
    float* Pt  = smem + OFF_P;
    float* At  = smem + OFF_A;
    float* hs  = smem + OFF_H;
    float* zs  = smem + OFF_Z;
    float* n2s = smem + OFF_N2;

    int tid = threadIdx.x;
    int n0 = blockIdx.x * FM;

    // load h tile [128][64] -> hs stride 65
#pragma unroll
    for (int q = 0; q < 8; q++) {
        int idx = tid + 256 * q;           // 0..2047 float4 slots
        int nd = idx >> 4;
        int j4 = idx & 15;
        int gn = n0 + nd;
        float4 v = make_float4(0.f, 0.f, 0.f, 0.f);
        if (gn < N_NODES) v = *(const float4*)&hin[gn * HDIM + j4 * 4];
        float* hr = hs + nd * 65 + j4 * 4;
        hr[0] = v.x; hr[1] = v.y; hr[2] = v.z; hr[3] = v.w;
    }
    __syncthreads();

    if (tid < FM) {
        float s = 0.f;
        const float* hr = hs + tid * 65;
#pragma unroll
        for (int j = 0; j < 64; j++) s = fmaf(hr[j], hr[j], s);
        n2s[tid] = s;
    }

    int ng = tid & 31;        // node group: nodes 4*ng .. 4*ng+3
    int kg = tid >> 5;        // k group: ks kg*5 .. kg*5+4
    int kbase = kg * 5;

    unsigned long long acc0[5], acc1[5];
#pragma unroll
    for (int c = 0; c < 5; c++) { acc0[c] = 0ull; acc1[c] = 0ull; }

    for (int pc = 0; pc < NPAIR; pc += KC) {
        __syncthreads();
        // stage A chunk: KC*80 floats, contiguous in g_Apack
        {
            const float4* src = (const float4*)&g_Apack[pc * 80];
#pragma unroll
            for (int q = 0; q < (KC * 80 / 4 + 255) / 256; q++) {
                int v = tid + 256 * q;
                if (v < KC * 80 / 4) *(float4*)&At[v * 4] = src[v];
            }
        }
        // build P chunk: P[pl][nd] = h[nd][i]*h[nd][j]
#pragma unroll
        for (int q = 0; q < KC * FM / 256; q++) {
            int t = tid + 256 * q;
            int pl = t >> 7;
            int nd = t & 127;
            int p = pc + pl;
            int i = __ldg(&g_pi[p]);
            int j = __ldg(&g_pj[p]);
            Pt[pl * FM + nd] = hs[nd * 65 + i] * hs[nd * 65 + j];
        }
        __syncthreads();

#pragma unroll 4
        for (int kk = 0; kk < KC; kk++) {
            double2 pd = *(const double2*)&Pt[kk * FM + ng * 4];
            unsigned long long p01 = __double_as_longlong(pd.x);
            unsigned long long p23 = __double_as_longlong(pd.y);
            const float* arow = At + kk * 80 + kbase * 2;
#pragma unroll
            for (int c = 0; c < 5; c++) {
                unsigned long long a = *(const unsigned long long*)&arow[c * 2];
                FMA_F32X2(acc0[c], p01, a, acc0[c]);
                FMA_F32X2(acc1[c], p23, a, acc1[c]);
            }
        }
    }

    // unpack accumulators -> zs[node][k]
#pragma unroll
    for (int c = 0; c < 5; c++) {
        int k = kbase + c;
        zs[(ng * 4 + 0) * C_OUT + k] = __uint_as_float((unsigned)(acc0[c] & 0xffffffffull));
        zs[(ng * 4 + 1) * C_OUT + k] = __uint_as_float((unsigned)(acc0[c] >> 32));
        zs[(ng * 4 + 2) * C_OUT + k] = __uint_as_float((unsigned)(acc1[c] & 0xffffffffull));
        zs[(ng * 4 + 3) * C_OUT + k] = __uint_as_float((unsigned)(acc1[c] >> 32));
    }
    __syncthreads();

    // per-node hyperbolic epilogue + log_softmax
    if (tid < FM) {
        int gn = n0 + tid;
        if (gn < N_NODES) {
            const float MAXN = 1.0f - 4e-3f;   // (1-PROJ_EPS)/sqrt(c), c=1
            float n2 = fmaxf(n2s[tid], 1e-15f);   // ||o|| = ||h||^2
            float pn = fminf(n2, MAXN);
            float t = atanhf(pn);
            float scale = t / n2;

            float u[C_OUT];
            float un2 = 0.f;
#pragma unroll
            for (int k = 0; k < C_OUT; k++) {
                float v = scale * zs[tid * C_OUT + k] + b1[k];
                u[k] = v;
                un2 = fmaf(v, v, un2);
            }
            float un = fmaxf(sqrtf(un2), 1e-15f);
            float th = tanhf(un);
            float g = fminf(th, MAXN) / un;

            float m = -INFINITY;
#pragma unroll
            for (int k = 0; k < C_OUT; k++) {
                u[k] *= g;
                m = fmaxf(m, u[k]);
            }
            float se = 0.f;
#pragma unroll
            for (int k = 0; k < C_OUT; k++) se += expf(u[k] - m);
            float lse = m + logf(se);
#pragma unroll
            for (int k = 0; k < C_OUT; k++) out[gn * C_OUT + k] = u[k] - lse;
        }
    }
}

// ---------------- launch ----------------
extern "C" void kernel_launch(void* const* d_in, const int* in_sizes, int n_in,
                              void* d_out, int out_size) {
    const float* x      = (const float*)d_in[0];
    const int*   row    = (const int*)d_in[1];
    const int*   col    = (const int*)d_in[2];
    const float* ew     = (const float*)d_in[3];
    const float* lin0_w = (const float*)d_in[4];
    const float* lin0_b = (const float*)d_in[5];
    const float* conv_w = (const float*)d_in[6];
    const float* lin1_w = (const float*)d_in[7];
    const float* lin1_b = (const float*)d_in[8];
    float* out = (float*)d_out;

    float* hA = nullptr;
    float* hB = nullptr;
    cudaGetSymbolAddress((void**)&hA, g_hA);
    cudaGetSymbolAddress((void**)&hB, g_hB);

    // CSR build
    zero_cnt_kernel<<<(N_NODES + 255) / 256, 256>>>();
    hist_kernel<<<(E_EDGES + 255) / 256, 256>>>(row);
    scan_kernel<<<1, 512>>>();
    scatter_kernel<<<(E_EDGES + 255) / 256, 256>>>(row, col, ew);

    // symmetric pair tables + packed A
    pairs_kernel<<<(NPAIR + 255) / 256, 256>>>();
    apack_kernel<<<(NPAIR * C_OUT + 255) / 256, 256>>>(lin1_w);

    // lin0 (writes g_h0 and g_hA)
    lin0_kernel<<<(N_NODES + 127) / 128, 256>>>(x, lin0_w, lin0_b);

    // 8 fused GCN2 layers, ping-pong hA/hB
    const float* hin = hA;
    float* hout = hB;
    for (int l = 0; l < L_LAYERS; l++) {
        float beta = logf(0.5f / (float)(l + 1) + 1.0f);
        layer_kernel<<<(N_NODES + 7) / 8, 256>>>(hin, hout, conv_w + l * HDIM * HDIM,
                                                 1.0f - beta, beta);
        const float* tmp = hin;
        hin = hout;
        hout = (float*)tmp;
    }

    // final fused symmetric-bilinear + hyperbolic + log_softmax
    cudaFuncSetAttribute(final_kernel, cudaFuncAttributeMaxDynamicSharedMemorySize,
                         FK_SMEM_BYTES);
    final_kernel<<<(N_NODES + FM - 1) / FM, 256, FK_SMEM_BYTES>>>(hin, lin1_b, out);
}